// round 5
// baseline (speedup 1.0000x reference)
#include <cuda_runtime.h>
#include <cstdint>

#define HNUM 12
#define DHEAD 64
#define BATCH 4
#define LQ 512
#define LK 512
#define DMODEL 768

// ---------------- scratch (device globals; no runtime alloc) ----------------
__device__ float g_Q[BATCH*HNUM*LQ*DHEAD];
__device__ float g_K[BATCH*HNUM*LK*DHEAD];
__device__ float g_V[BATCH*HNUM*LK*DHEAD];
__device__ uint32_t g_arc8[BATCH*512*512/4];
__device__ float g_lnk[3*DHEAD];
__device__ float g_lnv[3*DHEAD];

__device__ __forceinline__ float tf32_rna(float x) {
    uint32_t r;
    asm("cvt.rna.tf32.f32 %0, %1;" : "=r"(r) : "f"(x));
    return __uint_as_float(r);
}

#define MMA_TF32(d, a, b)                                                     \
    asm volatile("mma.sync.aligned.m16n8k8.row.col.f32.tf32.tf32.f32 "         \
        "{%0,%1,%2,%3}, {%4,%5,%6,%7}, {%8,%9}, {%0,%1,%2,%3};"                \
        : "+f"((d)[0]), "+f"((d)[1]), "+f"((d)[2]), "+f"((d)[3])               \
        : "r"(__float_as_uint((a)[0])), "r"(__float_as_uint((a)[1])),          \
          "r"(__float_as_uint((a)[2])), "r"(__float_as_uint((a)[3])),          \
          "r"(__float_as_uint((b)[0])), "r"(__float_as_uint((b)[1])))

#define CP_ASYNC16(dst, src) \
    asm volatile("cp.async.cg.shared.global [%0], [%1], 16;" :: "r"(dst), "l"(src) : "memory")
#define CP_COMMIT() asm volatile("cp.async.commit_group;" ::: "memory")
#define CP_WAIT1()  asm volatile("cp.async.wait_group 1;" ::: "memory")
#define CP_WAIT0()  asm volatile("cp.async.wait_group 0;" ::: "memory")

// ---------------- K1: layernorm the 3+3 relation embedding rows -------------
__global__ void ln_prep_kernel(const float* __restrict__ dpk, const float* __restrict__ dpv,
                               const float* __restrict__ kg, const float* __restrict__ kb,
                               const float* __restrict__ vg, const float* __restrict__ vb) {
    int w = threadIdx.x >> 5;
    int lane = threadIdx.x & 31;
    if (w >= 6) return;
    const float* src = (w < 3) ? dpk + w * DHEAD : dpv + (w - 3) * DHEAD;
    const float* g   = (w < 3) ? kg : vg;
    const float* be  = (w < 3) ? kb : vb;
    float* dst       = (w < 3) ? g_lnk + w * DHEAD : g_lnv + (w - 3) * DHEAD;
    float e0 = src[lane], e1 = src[lane + 32];
    float s = e0 + e1;
    #pragma unroll
    for (int o = 16; o; o >>= 1) s += __shfl_xor_sync(0xffffffffu, s, o);
    float mu = s * (1.0f / 64.0f);
    float d0 = e0 - mu, d1 = e1 - mu;
    float v = d0 * d0 + d1 * d1;
    #pragma unroll
    for (int o = 16; o; o >>= 1) v += __shfl_xor_sync(0xffffffffu, v, o);
    float rs = rsqrtf(v * (1.0f / 64.0f) + 1e-5f);
    dst[lane]      = d0 * rs * g[lane]      + be[lane];
    dst[lane + 32] = d1 * rs * g[lane + 32] + be[lane + 32];
}

// ---------------- K1b: pack arc int32 -> uint8 -------------------------------
__global__ __launch_bounds__(256) void arc_pack_kernel(const int* __restrict__ arc) {
    int i = blockIdx.x * 256 + threadIdx.x;          // over 262144 uint32 outputs
    const int4 a = *(const int4*)&arc[i * 4];
    g_arc8[i] = (uint32_t)a.x | ((uint32_t)a.y << 8) |
                ((uint32_t)a.z << 16) | ((uint32_t)a.w << 24);
}

// ---------------- K2: split-tf32 mma.sync QKV GEMM ---------------------------
#define A_STRIDE 36
#define B_STRIDE 132
#define STAGE_FLOATS (128 * A_STRIDE + 32 * B_STRIDE)
#define GEMM_SMEM_BYTES (2 * STAGE_FLOATS * 4)

__global__ __launch_bounds__(256, 2) void qkv_gemm_mma_kernel(
    const float* __restrict__ hidden, const float* __restrict__ ctx,
    const float* __restrict__ Wq, const float* __restrict__ bq,
    const float* __restrict__ Wk, const float* __restrict__ bk,
    const float* __restrict__ Wv, const float* __restrict__ bv) {
    extern __shared__ float smem[];

    int sel = blockIdx.z;
    const float* X    = (sel == 0) ? hidden : ctx;
    const float* W    = (sel == 0) ? Wq : (sel == 1 ? Wk : Wv);
    const float* bias = (sel == 0) ? bq : (sel == 1 ? bk : bv);
    float* Out        = (sel == 0) ? g_Q : (sel == 1 ? g_K : g_V);

    int m0 = blockIdx.x * 128;
    int n0 = blockIdx.y * 128;
    int t = threadIdx.x;
    int w = t >> 5;
    int lane = t & 31;
    int gid = lane >> 2;
    int tid4 = lane & 3;
    int wm = w >> 2;
    int wn = w & 3;

    auto load_chunk = [&](int c, int s) {
        int k0 = c * 32;
        float* sA = smem + s * STAGE_FLOATS;
        float* sB = sA + 128 * A_STRIDE;
        #pragma unroll
        for (int it = 0; it < 4; it++) {
            int idx = it * 256 + t;
            int r = idx >> 3, c4 = (idx & 7) << 2;
            uint32_t dst = (uint32_t)__cvta_generic_to_shared(&sA[r * A_STRIDE + c4]);
            CP_ASYNC16(dst, &X[(size_t)(m0 + r) * DMODEL + k0 + c4]);
        }
        #pragma unroll
        for (int it = 0; it < 4; it++) {
            int idx = it * 256 + t;
            int kr = idx >> 5, c4 = (idx & 31) << 2;
            uint32_t dst = (uint32_t)__cvta_generic_to_shared(&sB[kr * B_STRIDE + c4]);
            CP_ASYNC16(dst, &W[(size_t)(k0 + kr) * DMODEL + n0 + c4]);
        }
        CP_COMMIT();
    };

    float acc[4][4][4];
    #pragma unroll
    for (int mt = 0; mt < 4; mt++)
        #pragma unroll
        for (int nt = 0; nt < 4; nt++)
            #pragma unroll
            for (int f = 0; f < 4; f++) acc[mt][nt][f] = 0.f;

    load_chunk(0, 0);
    load_chunk(1, 1);
    CP_WAIT1();
    __syncthreads();

    for (int c = 0; c < 24; c++) {
        int s = c & 1;
        const float* sA = smem + s * STAGE_FLOATS;
        const float* sB = sA + 128 * A_STRIDE;
        #pragma unroll
        for (int ks = 0; ks < 4; ks++) {
            int k = ks * 8 + tid4;
            float ah[4][4], al[4][4];
            #pragma unroll
            for (int mt = 0; mt < 4; mt++) {
                int r = wm * 64 + mt * 16 + gid;
                float a0 = sA[r * A_STRIDE + k];
                float a1 = sA[(r + 8) * A_STRIDE + k];
                float a2 = sA[r * A_STRIDE + k + 4];
                float a3 = sA[(r + 8) * A_STRIDE + k + 4];
                ah[mt][0] = tf32_rna(a0); al[mt][0] = a0 - ah[mt][0];
                ah[mt][1] = tf32_rna(a1); al[mt][1] = a1 - ah[mt][1];
                ah[mt][2] = tf32_rna(a2); al[mt][2] = a2 - ah[mt][2];
                ah[mt][3] = tf32_rna(a3); al[mt][3] = a3 - ah[mt][3];
            }
            #pragma unroll
            for (int nt = 0; nt < 4; nt++) {
                int n = wn * 32 + nt * 8 + gid;
                float b0 = sB[k * B_STRIDE + n];
                float b1 = sB[(k + 4) * B_STRIDE + n];
                float bh[2], bl[2];
                bh[0] = tf32_rna(b0); bl[0] = b0 - bh[0];
                bh[1] = tf32_rna(b1); bl[1] = b1 - bh[1];
                #pragma unroll
                for (int mt = 0; mt < 4; mt++) {
                    MMA_TF32(acc[mt][nt], ah[mt], bh);
                    MMA_TF32(acc[mt][nt], ah[mt], bl);
                    MMA_TF32(acc[mt][nt], al[mt], bh);
                }
            }
        }
        __syncthreads();
        if (c + 2 < 24) {
            load_chunk(c + 2, s);
            CP_WAIT1();
        } else {
            CP_WAIT0();
        }
        __syncthreads();
    }

    float bv2[4][2];
    #pragma unroll
    for (int nt = 0; nt < 4; nt++) {
        int col = n0 + wn * 32 + nt * 8 + tid4 * 2;
        bv2[nt][0] = bias[col];
        bv2[nt][1] = bias[col + 1];
    }
    #pragma unroll
    for (int mt = 0; mt < 4; mt++) {
        #pragma unroll
        for (int half = 0; half < 2; half++) {
            int row = m0 + wm * 64 + mt * 16 + gid + half * 8;
            int b = row >> 9, tok = row & 511;
            #pragma unroll
            for (int nt = 0; nt < 4; nt++) {
                int col = n0 + wn * 32 + nt * 8 + tid4 * 2;
                int head = col >> 6, dh = col & 63;
                float2 v;
                v.x = acc[mt][nt][half * 2 + 0] + bv2[nt][0];
                v.y = acc[mt][nt][half * 2 + 1] + bv2[nt][1];
                *(float2*)&Out[((size_t)(b * HNUM + head) * 512 + tok) * 64 + dh] = v;
            }
        }
    }
}

// ---------------- K3: mma.sync tf32 flash attention --------------------------
// grid (8 q-tiles of 64, 48 bh), 256 threads (8 warps).
// Warp grid for mma phases: wm = w>>1 (16-row slab), wn = w&1 (32-col slab).
// Softmax: warp w owns rows w*8 .. w*8+7.
#define QS 68
#define KS 68
#define VS 69
#define SS 68
#define SM_Q     0
#define SM_K     (SM_Q + 64*QS)
#define SM_V     (SM_K + 64*KS)
#define SM_S     (SM_V + 64*VS)
#define SM_MASK  (SM_S + 64*SS)
#define SM_SCALE (SM_MASK + 512)
#define SM_INV   (SM_SCALE + 64)
#define SM_PW    (SM_INV + 64)
#define SM_QDP   (SM_PW + 64*4)
#define SM_FLOATS (SM_QDP + 64*4)
#define SM_ARC_BYTES (64*64)
#define ATTN_SMEM_BYTES (SM_FLOATS*4 + SM_ARC_BYTES)

__global__ __launch_bounds__(256, 2) void attn_mma_kernel(
    const float* __restrict__ mask, float* __restrict__ out) {
    extern __shared__ float sm[];
    float* sQ = sm + SM_Q;
    float* sK = sm + SM_K;
    float* sV = sm + SM_V;
    float* sS = sm + SM_S;
    float* sMask = sm + SM_MASK;
    float* sScale = sm + SM_SCALE;
    float* sInv = sm + SM_INV;
    float* sPw = sm + SM_PW;
    float* sQdp = sm + SM_QDP;
    unsigned char* sArc = (unsigned char*)(sm + SM_FLOATS);

    int bh = blockIdx.y;
    int b = bh / HNUM, h = bh % HNUM;
    int q0 = blockIdx.x * 64;
    int t = threadIdx.x;
    int w = t >> 5;
    int lane = t & 31;
    int gid = lane >> 2;
    int tid4 = lane & 3;
    int wm = w >> 1;
    int wn = w & 1;

    const float* Qbase = g_Q + ((size_t)bh * 512 + q0) * 64;
    const float* Kbase = g_K + (size_t)bh * 512 * 64;
    const float* Vbase = g_V + (size_t)bh * 512 * 64;

    // load Q (tf32-rounded), mask
    for (int i = t; i < 64 * 16; i += 256) {
        int q = i >> 4, d4 = (i & 15) << 2;
        float4 v = *(const float4*)&Qbase[q * 64 + d4];
        sQ[q * QS + d4 + 0] = tf32_rna(v.x);
        sQ[q * QS + d4 + 1] = tf32_rna(v.y);
        sQ[q * QS + d4 + 2] = tf32_rna(v.z);
        sQ[q * QS + d4 + 3] = tf32_rna(v.w);
    }
    for (int i = t; i < 512; i += 256) sMask[i] = mask[b * 512 + i];
    __syncthreads();

    // qdp for this warp's softmax rows (reads own rows only -> no extra sync)
    #pragma unroll
    for (int ri = 0; ri < 8; ri++) {
        int row = w * 8 + ri;
        float q0v = sQ[row * QS + lane], q1v = sQ[row * QS + lane + 32];
        float s0 = q0v * g_lnk[lane]       + q1v * g_lnk[lane + 32];
        float s1 = q0v * g_lnk[64 + lane]  + q1v * g_lnk[96 + lane];
        float s2 = q0v * g_lnk[128 + lane] + q1v * g_lnk[160 + lane];
        #pragma unroll
        for (int o = 16; o; o >>= 1) {
            s0 += __shfl_xor_sync(0xffffffffu, s0, o);
            s1 += __shfl_xor_sync(0xffffffffu, s1, o);
            s2 += __shfl_xor_sync(0xffffffffu, s2, o);
        }
        if (lane == 0) {
            sQdp[row * 4 + 0] = s0; sQdp[row * 4 + 1] = s1;
            sQdp[row * 4 + 2] = s2; sQdp[row * 4 + 3] = 0.f;
        }
    }

    float m_run[8], rsum[8], pw0[8], pw1[8], pw2[8];
    #pragma unroll
    for (int ri = 0; ri < 8; ri++) {
        m_run[ri] = -1e30f; rsum[ri] = 0.f;
        pw0[ri] = pw1[ri] = pw2[ri] = 0.f;
    }
    float oacc[4][4];
    #pragma unroll
    for (int nt = 0; nt < 4; nt++)
        #pragma unroll
        for (int f = 0; f < 4; f++) oacc[nt][f] = 0.f;

    for (int kt = 0; kt < 8; kt++) {
        __syncthreads();
        // load K, V (tf32-rounded), arc bytes
        for (int i = t; i < 64 * 16; i += 256) {
            int k = i >> 4, d4 = (i & 15) << 2;
            float4 kv = *(const float4*)&Kbase[(size_t)(kt * 64 + k) * 64 + d4];
            sK[k * KS + d4 + 0] = tf32_rna(kv.x);
            sK[k * KS + d4 + 1] = tf32_rna(kv.y);
            sK[k * KS + d4 + 2] = tf32_rna(kv.z);
            sK[k * KS + d4 + 3] = tf32_rna(kv.w);
            float4 vv = *(const float4*)&Vbase[(size_t)(kt * 64 + k) * 64 + d4];
            sV[k * VS + d4 + 0] = tf32_rna(vv.x);
            sV[k * VS + d4 + 1] = tf32_rna(vv.y);
            sV[k * VS + d4 + 2] = tf32_rna(vv.z);
            sV[k * VS + d4 + 3] = tf32_rna(vv.w);
        }
        for (int i = t; i < 64 * 16; i += 256) {
            int q = i >> 4, j = i & 15;
            ((uint32_t*)sArc)[q * 16 + j] =
                g_arc8[(size_t)(b * 512 + q0 + q) * 128 + kt * 16 + j];
        }
        __syncthreads();

        // QK^T via mma: warp computes S[wm*16..+16][wn*32..+32]
        float sfr[4][4];
        #pragma unroll
        for (int nt = 0; nt < 4; nt++)
            #pragma unroll
            for (int f = 0; f < 4; f++) sfr[nt][f] = 0.f;
        #pragma unroll
        for (int ks = 0; ks < 8; ks++) {
            int k = ks * 8 + tid4;
            float afr[4];
            int r = wm * 16 + gid;
            afr[0] = sQ[r * QS + k];
            afr[1] = sQ[(r + 8) * QS + k];
            afr[2] = sQ[r * QS + k + 4];
            afr[3] = sQ[(r + 8) * QS + k + 4];
            #pragma unroll
            for (int nt = 0; nt < 4; nt++) {
                int n = wn * 32 + nt * 8 + gid;
                float bfr[2];
                bfr[0] = sK[n * KS + k];
                bfr[1] = sK[n * KS + k + 4];
                MMA_TF32(sfr[nt], afr, bfr);
            }
        }
        #pragma unroll
        for (int nt = 0; nt < 4; nt++) {
            int col = wn * 32 + nt * 8 + tid4 * 2;
            int r = wm * 16 + gid;
            *(float2*)&sS[r * SS + col]       = make_float2(sfr[nt][0], sfr[nt][1]);
            *(float2*)&sS[(r + 8) * SS + col] = make_float2(sfr[nt][2], sfr[nt][3]);
        }
        __syncthreads();

        // online softmax: warp w owns rows w*8..+7; lane covers cols 2l, 2l+1
        #pragma unroll
        for (int ri = 0; ri < 8; ri++) {
            int row = w * 8 + ri;
            float2 sv = *(float2*)&sS[row * SS + 2 * lane];
            int a0 = sArc[row * 64 + 2 * lane];
            int a1 = sArc[row * 64 + 2 * lane + 1];
            float x = sv.x * 0.125f + sQdp[row * 4 + a0] + sMask[kt * 64 + 2 * lane];
            float y = sv.y * 0.125f + sQdp[row * 4 + a1] + sMask[kt * 64 + 2 * lane + 1];
            float tm = fmaxf(x, y);
            #pragma unroll
            for (int o = 16; o; o >>= 1) tm = fmaxf(tm, __shfl_xor_sync(0xffffffffu, tm, o));
            float nm = fmaxf(m_run[ri], tm);
            float sc = __expf(m_run[ri] - nm);
            m_run[ri] = nm;
            float px = __expf(x - nm);
            float py = __expf(y - nm);
            rsum[ri] = rsum[ri] * sc + px + py;
            pw0[ri] = pw0[ri] * sc + (a0 == 0 ? px : 0.f) + (a1 == 0 ? py : 0.f);
            pw1[ri] = pw1[ri] * sc + (a0 == 1 ? px : 0.f) + (a1 == 1 ? py : 0.f);
            pw2[ri] = pw2[ri] * sc + (a0 == 2 ? px : 0.f) + (a1 == 2 ? py : 0.f);
            *(float2*)&sS[row * SS + 2 * lane] = make_float2(tf32_rna(px), tf32_rna(py));
            if (lane == 0) sScale[row] = sc;
        }
        __syncthreads();

        // P@V via mma: rescale then accumulate
        float sc0 = sScale[wm * 16 + gid];
        float sc1 = sScale[wm * 16 + 8 + gid];
        #pragma unroll
        for (int nt = 0; nt < 4; nt++) {
            oacc[nt][0] *= sc0; oacc[nt][1] *= sc0;
            oacc[nt][2] *= sc1; oacc[nt][3] *= sc1;
        }
        #pragma unroll
        for (int ks = 0; ks < 8; ks++) {
            int k = ks * 8 + tid4;          // key index
            float afr[4];
            int r = wm * 16 + gid;
            afr[0] = sS[r * SS + k];
            afr[1] = sS[(r + 8) * SS + k];
            afr[2] = sS[r * SS + k + 4];
            afr[3] = sS[(r + 8) * SS + k + 4];
            #pragma unroll
            for (int nt = 0; nt < 4; nt++) {
                int n = wn * 32 + nt * 8 + gid;   // d index
                float bfr[2];
                bfr[0] = sV[k * VS + n];
                bfr[1] = sV[(k + 4) * VS + n];
                MMA_TF32(oacc[nt], afr, bfr);
            }
        }
    }

    // final reductions
    #pragma unroll
    for (int ri = 0; ri < 8; ri++) {
        int row = w * 8 + ri;
        float su = rsum[ri], c0 = pw0[ri], c1 = pw1[ri], c2 = pw2[ri];
        #pragma unroll
        for (int o = 16; o; o >>= 1) {
            su += __shfl_xor_sync(0xffffffffu, su, o);
            c0 += __shfl_xor_sync(0xffffffffu, c0, o);
            c1 += __shfl_xor_sync(0xffffffffu, c1, o);
            c2 += __shfl_xor_sync(0xffffffffu, c2, o);
        }
        if (lane == 0) {
            sInv[row] = 1.f / su;
            sPw[row * 4 + 0] = c0; sPw[row * 4 + 1] = c1; sPw[row * 4 + 2] = c2;
        }
    }
    __syncthreads();

    // output
    int r0 = wm * 16 + gid, r1 = r0 + 8;
    float inv0 = sInv[r0], inv1 = sInv[r1];
    float p00 = sPw[r0*4+0], p01 = sPw[r0*4+1], p02 = sPw[r0*4+2];
    float p10 = sPw[r1*4+0], p11 = sPw[r1*4+1], p12 = sPw[r1*4+2];
    #pragma unroll
    for (int nt = 0; nt < 4; nt++) {
        int col = wn * 32 + nt * 8 + tid4 * 2;
        float lv0a = g_lnv[col],     lv0b = g_lnv[col + 1];
        float lv1a = g_lnv[64+col],  lv1b = g_lnv[64+col+1];
        float lv2a = g_lnv[128+col], lv2b = g_lnv[128+col+1];
        float2 v0, v1;
        v0.x = (oacc[nt][0] + p00*lv0a + p01*lv1a + p02*lv2a) * inv0;
        v0.y = (oacc[nt][1] + p00*lv0b + p01*lv1b + p02*lv2b) * inv0;
        v1.x = (oacc[nt][2] + p10*lv0a + p11*lv1a + p12*lv2a) * inv1;
        v1.y = (oacc[nt][3] + p10*lv0b + p11*lv1b + p12*lv2b) * inv1;
        *(float2*)&out[(size_t)(b * 512 + q0 + r0) * 768 + h * 64 + col] = v0;
        *(float2*)&out[(size_t)(b * 512 + q0 + r1) * 768 + h * 64 + col] = v1;
    }
}

// ---------------- launcher ----------------------------------------------------
extern "C" void kernel_launch(void* const* d_in, const int* in_sizes, int n_in,
                              void* d_out, int out_size) {
    const float* hidden = (const float*)d_in[0];
    const float* ctx    = (const float*)d_in[1];
    const float* mask   = (const float*)d_in[2];
    const int*   arc    = (const int*)d_in[3];
    const float* Wq = (const float*)d_in[4];  const float* bq = (const float*)d_in[5];
    const float* Wk = (const float*)d_in[6];  const float* bk = (const float*)d_in[7];
    const float* Wv = (const float*)d_in[8];  const float* bv = (const float*)d_in[9];
    const float* dpk = (const float*)d_in[10]; const float* dpv = (const float*)d_in[11];
    const float* lkg = (const float*)d_in[12]; const float* lkb = (const float*)d_in[13];
    const float* lvg = (const float*)d_in[14]; const float* lvb = (const float*)d_in[15];
    float* out = (float*)d_out;

    ln_prep_kernel<<<1, 192>>>(dpk, dpv, lkg, lkb, lvg, lvb);
    arc_pack_kernel<<<1024, 256>>>(arc);

    cudaFuncSetAttribute(qkv_gemm_mma_kernel, cudaFuncAttributeMaxDynamicSharedMemorySize,
                         GEMM_SMEM_BYTES);
    qkv_gemm_mma_kernel<<<dim3(16, 6, 3), 256, GEMM_SMEM_BYTES>>>(
        hidden, ctx, Wq, bq, Wk, bk, Wv, bv);

    cudaFuncSetAttribute(attn_mma_kernel, cudaFuncAttributeMaxDynamicSharedMemorySize,
                         ATTN_SMEM_BYTES);
    attn_mma_kernel<<<dim3(8, 48), 256, ATTN_SMEM_BYTES>>>(mask, out);
}

// round 6
// speedup vs baseline: 2.3313x; 2.3313x over previous
#include <cuda_runtime.h>
#include <cstdint>

#define HNUM 12
#define DHEAD 64
#define BATCH 4
#define LQ 512
#define LK 512
#define DMODEL 768

// ---------------- scratch (device globals; no runtime alloc) ----------------
__device__ float g_Q[BATCH*HNUM*LQ*DHEAD];
__device__ float g_K[BATCH*HNUM*LK*DHEAD];
__device__ float g_V[BATCH*HNUM*LK*DHEAD];
__device__ float g_S[(size_t)BATCH*HNUM*LQ*LK];
__device__ float g_P[(size_t)BATCH*HNUM*LQ*LK];
__device__ float g_PW[BATCH*HNUM*LQ*4];
__device__ uint32_t g_arc8[BATCH*512*512/4];
__device__ float g_lnk[3*DHEAD];
__device__ float g_lnv[3*DHEAD];

__device__ __forceinline__ float tf32_rna(float x) {
    uint32_t r;
    asm("cvt.rna.tf32.f32 %0, %1;" : "=r"(r) : "f"(x));
    return __uint_as_float(r);
}

#define MMA_TF32(d, a, b)                                                     \
    asm volatile("mma.sync.aligned.m16n8k8.row.col.f32.tf32.tf32.f32 "         \
        "{%0,%1,%2,%3}, {%4,%5,%6,%7}, {%8,%9}, {%0,%1,%2,%3};"                \
        : "+f"((d)[0]), "+f"((d)[1]), "+f"((d)[2]), "+f"((d)[3])               \
        : "r"(__float_as_uint((a)[0])), "r"(__float_as_uint((a)[1])),          \
          "r"(__float_as_uint((a)[2])), "r"(__float_as_uint((a)[3])),          \
          "r"(__float_as_uint((b)[0])), "r"(__float_as_uint((b)[1])))

#define CP_ASYNC16(dst, src) \
    asm volatile("cp.async.cg.shared.global [%0], [%1], 16;" :: "r"(dst), "l"(src) : "memory")
#define CP_COMMIT() asm volatile("cp.async.commit_group;" ::: "memory")
#define CP_WAIT1()  asm volatile("cp.async.wait_group 1;" ::: "memory")
#define CP_WAIT0()  asm volatile("cp.async.wait_group 0;" ::: "memory")

// ---------------- K1: layernorm the 3+3 relation embedding rows -------------
__global__ void ln_prep_kernel(const float* __restrict__ dpk, const float* __restrict__ dpv,
                               const float* __restrict__ kg, const float* __restrict__ kb,
                               const float* __restrict__ vg, const float* __restrict__ vb) {
    int w = threadIdx.x >> 5;
    int lane = threadIdx.x & 31;
    if (w >= 6) return;
    const float* src = (w < 3) ? dpk + w * DHEAD : dpv + (w - 3) * DHEAD;
    const float* g   = (w < 3) ? kg : vg;
    const float* be  = (w < 3) ? kb : vb;
    float* dst       = (w < 3) ? g_lnk + w * DHEAD : g_lnv + (w - 3) * DHEAD;
    float e0 = src[lane], e1 = src[lane + 32];
    float s = e0 + e1;
    #pragma unroll
    for (int o = 16; o; o >>= 1) s += __shfl_xor_sync(0xffffffffu, s, o);
    float mu = s * (1.0f / 64.0f);
    float d0 = e0 - mu, d1 = e1 - mu;
    float v = d0 * d0 + d1 * d1;
    #pragma unroll
    for (int o = 16; o; o >>= 1) v += __shfl_xor_sync(0xffffffffu, v, o);
    float rs = rsqrtf(v * (1.0f / 64.0f) + 1e-5f);
    dst[lane]      = d0 * rs * g[lane]      + be[lane];
    dst[lane + 32] = d1 * rs * g[lane + 32] + be[lane + 32];
}

// ---------------- K1b: pack arc int32 -> uint8 -------------------------------
__global__ __launch_bounds__(256) void arc_pack_kernel(const int* __restrict__ arc) {
    int i = blockIdx.x * 256 + threadIdx.x;
    const int4 a = *(const int4*)&arc[i * 4];
    g_arc8[i] = (uint32_t)a.x | ((uint32_t)a.y << 8) |
                ((uint32_t)a.z << 16) | ((uint32_t)a.w << 24);
}

// ---------------- K2: tf32(rna) mma.sync QKV GEMM ----------------------------
#define A_STRIDE 36
#define B_STRIDE 132
#define STAGE_FLOATS (128 * A_STRIDE + 32 * B_STRIDE)
#define GEMM_SMEM_BYTES (2 * STAGE_FLOATS * 4)

__global__ __launch_bounds__(256, 2) void qkv_gemm_mma_kernel(
    const float* __restrict__ hidden, const float* __restrict__ ctx,
    const float* __restrict__ Wq, const float* __restrict__ bq,
    const float* __restrict__ Wk, const float* __restrict__ bk,
    const float* __restrict__ Wv, const float* __restrict__ bv) {
    extern __shared__ float smem[];

    int sel = blockIdx.z;
    const float* X    = (sel == 0) ? hidden : ctx;
    const float* W    = (sel == 0) ? Wq : (sel == 1 ? Wk : Wv);
    const float* bias = (sel == 0) ? bq : (sel == 1 ? bk : bv);
    float* Out        = (sel == 0) ? g_Q : (sel == 1 ? g_K : g_V);

    int m0 = blockIdx.x * 128;
    int n0 = blockIdx.y * 128;
    int t = threadIdx.x;
    int w = t >> 5;
    int lane = t & 31;
    int gid = lane >> 2;
    int tid4 = lane & 3;
    int wm = w >> 2;
    int wn = w & 3;

    auto load_chunk = [&](int c, int s) {
        int k0 = c * 32;
        float* sA = smem + s * STAGE_FLOATS;
        float* sB = sA + 128 * A_STRIDE;
        #pragma unroll
        for (int it = 0; it < 4; it++) {
            int idx = it * 256 + t;
            int r = idx >> 3, c4 = (idx & 7) << 2;
            uint32_t dst = (uint32_t)__cvta_generic_to_shared(&sA[r * A_STRIDE + c4]);
            CP_ASYNC16(dst, &X[(size_t)(m0 + r) * DMODEL + k0 + c4]);
        }
        #pragma unroll
        for (int it = 0; it < 4; it++) {
            int idx = it * 256 + t;
            int kr = idx >> 5, c4 = (idx & 31) << 2;
            uint32_t dst = (uint32_t)__cvta_generic_to_shared(&sB[kr * B_STRIDE + c4]);
            CP_ASYNC16(dst, &W[(size_t)(k0 + kr) * DMODEL + n0 + c4]);
        }
        CP_COMMIT();
    };

    float acc[4][4][4];
    #pragma unroll
    for (int mt = 0; mt < 4; mt++)
        #pragma unroll
        for (int nt = 0; nt < 4; nt++)
            #pragma unroll
            for (int f = 0; f < 4; f++) acc[mt][nt][f] = 0.f;

    load_chunk(0, 0);
    load_chunk(1, 1);
    CP_WAIT1();
    __syncthreads();

    for (int c = 0; c < 24; c++) {
        int s = c & 1;
        const float* sA = smem + s * STAGE_FLOATS;
        const float* sB = sA + 128 * A_STRIDE;
        #pragma unroll
        for (int ks = 0; ks < 4; ks++) {
            int k = ks * 8 + tid4;
            float afr[4][4];
            #pragma unroll
            for (int mt = 0; mt < 4; mt++) {
                int r = wm * 64 + mt * 16 + gid;
                afr[mt][0] = tf32_rna(sA[r * A_STRIDE + k]);
                afr[mt][1] = tf32_rna(sA[(r + 8) * A_STRIDE + k]);
                afr[mt][2] = tf32_rna(sA[r * A_STRIDE + k + 4]);
                afr[mt][3] = tf32_rna(sA[(r + 8) * A_STRIDE + k + 4]);
            }
            #pragma unroll
            for (int nt = 0; nt < 4; nt++) {
                int n = wn * 32 + nt * 8 + gid;
                float bfr[2];
                bfr[0] = tf32_rna(sB[k * B_STRIDE + n]);
                bfr[1] = tf32_rna(sB[(k + 4) * B_STRIDE + n]);
                #pragma unroll
                for (int mt = 0; mt < 4; mt++)
                    MMA_TF32(acc[mt][nt], afr[mt], bfr);
            }
        }
        __syncthreads();
        if (c + 2 < 24) {
            load_chunk(c + 2, s);
            CP_WAIT1();
        } else {
            CP_WAIT0();
        }
        __syncthreads();
    }

    float bv2[4][2];
    #pragma unroll
    for (int nt = 0; nt < 4; nt++) {
        int col = n0 + wn * 32 + nt * 8 + tid4 * 2;
        bv2[nt][0] = bias[col];
        bv2[nt][1] = bias[col + 1];
    }
    #pragma unroll
    for (int mt = 0; mt < 4; mt++) {
        #pragma unroll
        for (int half = 0; half < 2; half++) {
            int row = m0 + wm * 64 + mt * 16 + gid + half * 8;
            int b = row >> 9, tok = row & 511;
            #pragma unroll
            for (int nt = 0; nt < 4; nt++) {
                int col = n0 + wn * 32 + nt * 8 + tid4 * 2;
                int head = col >> 6, dh = col & 63;
                float2 v;
                v.x = acc[mt][nt][half * 2 + 0] + bv2[nt][0];
                v.y = acc[mt][nt][half * 2 + 1] + bv2[nt][1];
                *(float2*)&Out[((size_t)(b * HNUM + head) * 512 + tok) * 64 + dh] = v;
            }
        }
    }
}

// ---------------- KA: S = Q K^T  (raw dot, no scale) -------------------------
// grid (4 q-tiles of 128, 4 k-tiles of 128, 48 bh), 256 threads.
#define QK_STRIDE 68
#define QK_SMEM_BYTES (2 * 128 * QK_STRIDE * 4)   // 69632

__global__ __launch_bounds__(256, 1) void qk_kernel() {
    extern __shared__ float sm[];
    float* sQ = sm;
    float* sK = sm + 128 * QK_STRIDE;

    int bh = blockIdx.z;
    int q0 = blockIdx.x * 128;
    int k0 = blockIdx.y * 128;
    int t = threadIdx.x;
    int w = t >> 5;
    int lane = t & 31;
    int gid = lane >> 2;
    int tid4 = lane & 3;
    int wm = w >> 2;       // 0..1 (64 q rows)
    int wn = w & 3;        // 0..3 (32 k cols)

    const float* Qbase = g_Q + ((size_t)bh * 512 + q0) * 64;
    const float* Kbase = g_K + ((size_t)bh * 512 + k0) * 64;

    for (int i = t; i < 128 * 16; i += 256) {
        int r = i >> 4, c4 = (i & 15) << 2;
        float4 qv = *(const float4*)&Qbase[r * 64 + c4];
        sQ[r * QK_STRIDE + c4 + 0] = tf32_rna(qv.x);
        sQ[r * QK_STRIDE + c4 + 1] = tf32_rna(qv.y);
        sQ[r * QK_STRIDE + c4 + 2] = tf32_rna(qv.z);
        sQ[r * QK_STRIDE + c4 + 3] = tf32_rna(qv.w);
        float4 kv = *(const float4*)&Kbase[r * 64 + c4];
        sK[r * QK_STRIDE + c4 + 0] = tf32_rna(kv.x);
        sK[r * QK_STRIDE + c4 + 1] = tf32_rna(kv.y);
        sK[r * QK_STRIDE + c4 + 2] = tf32_rna(kv.z);
        sK[r * QK_STRIDE + c4 + 3] = tf32_rna(kv.w);
    }
    __syncthreads();

    float acc[4][4][4];
    #pragma unroll
    for (int mt = 0; mt < 4; mt++)
        #pragma unroll
        for (int nt = 0; nt < 4; nt++)
            #pragma unroll
            for (int f = 0; f < 4; f++) acc[mt][nt][f] = 0.f;

    #pragma unroll
    for (int ks = 0; ks < 8; ks++) {
        int k = ks * 8 + tid4;
        float afr[4][4];
        #pragma unroll
        for (int mt = 0; mt < 4; mt++) {
            int r = wm * 64 + mt * 16 + gid;
            afr[mt][0] = sQ[r * QK_STRIDE + k];
            afr[mt][1] = sQ[(r + 8) * QK_STRIDE + k];
            afr[mt][2] = sQ[r * QK_STRIDE + k + 4];
            afr[mt][3] = sQ[(r + 8) * QK_STRIDE + k + 4];
        }
        #pragma unroll
        for (int nt = 0; nt < 4; nt++) {
            int n = wn * 32 + nt * 8 + gid;
            float bfr[2];
            bfr[0] = sK[n * QK_STRIDE + k];
            bfr[1] = sK[n * QK_STRIDE + k + 4];
            #pragma unroll
            for (int mt = 0; mt < 4; mt++)
                MMA_TF32(acc[mt][nt], afr[mt], bfr);
        }
    }

    #pragma unroll
    for (int mt = 0; mt < 4; mt++) {
        #pragma unroll
        for (int half = 0; half < 2; half++) {
            int q = q0 + wm * 64 + mt * 16 + gid + half * 8;
            float* Srow = g_S + ((size_t)bh * 512 + q) * 512;
            #pragma unroll
            for (int nt = 0; nt < 4; nt++) {
                int col = k0 + wn * 32 + nt * 8 + tid4 * 2;
                *(float2*)&Srow[col] =
                    make_float2(acc[mt][nt][half * 2], acc[mt][nt][half * 2 + 1]);
            }
        }
    }
}

// ---------------- KB: row softmax + arc masses, writes normalized P ----------
// grid (64, 48), 256 threads; 1 warp = 1 row.
__global__ __launch_bounds__(256) void softmax_kernel(const float* __restrict__ mask) {
    int bh = blockIdx.y;
    int b = bh / HNUM;
    int q = blockIdx.x * 8 + (threadIdx.x >> 5);
    int lane = threadIdx.x & 31;

    // qdp = Q[row] . lnk[r]
    const float* Qrow = g_Q + ((size_t)bh * 512 + q) * 64;
    float q0v = Qrow[lane], q1v = Qrow[lane + 32];
    float s0 = q0v * g_lnk[lane]       + q1v * g_lnk[lane + 32];
    float s1 = q0v * g_lnk[64 + lane]  + q1v * g_lnk[96 + lane];
    float s2 = q0v * g_lnk[128 + lane] + q1v * g_lnk[160 + lane];
    #pragma unroll
    for (int o = 16; o; o >>= 1) {
        s0 += __shfl_xor_sync(0xffffffffu, s0, o);
        s1 += __shfl_xor_sync(0xffffffffu, s1, o);
        s2 += __shfl_xor_sync(0xffffffffu, s2, o);
    }
    float qd[4] = {s0, s1, s2, 0.f};

    const float* Srow = g_S + ((size_t)bh * 512 + q) * 512;
    const uint32_t* arcw = g_arc8 + ((size_t)(b * 512 + q)) * 128 + lane * 4;
    const float* mrow = mask + b * 512 + lane * 16;

    float x[16];
    int a[16];
    #pragma unroll
    for (int j = 0; j < 4; j++) {
        float4 sv = *(const float4*)&Srow[lane * 16 + j * 4];
        float4 mv = *(const float4*)&mrow[j * 4];
        uint32_t aw = arcw[j];
        a[j*4+0] = aw & 3;          a[j*4+1] = (aw >> 8) & 3;
        a[j*4+2] = (aw >> 16) & 3;  a[j*4+3] = (aw >> 24) & 3;
        x[j*4+0] = sv.x * 0.125f + qd[a[j*4+0]] + mv.x;
        x[j*4+1] = sv.y * 0.125f + qd[a[j*4+1]] + mv.y;
        x[j*4+2] = sv.z * 0.125f + qd[a[j*4+2]] + mv.z;
        x[j*4+3] = sv.w * 0.125f + qd[a[j*4+3]] + mv.w;
    }
    float mx = x[0];
    #pragma unroll
    for (int j = 1; j < 16; j++) mx = fmaxf(mx, x[j]);
    #pragma unroll
    for (int o = 16; o; o >>= 1) mx = fmaxf(mx, __shfl_xor_sync(0xffffffffu, mx, o));

    float sum = 0.f, p0 = 0.f, p1 = 0.f, p2 = 0.f;
    #pragma unroll
    for (int j = 0; j < 16; j++) {
        float p = __expf(x[j] - mx);
        x[j] = p;
        sum += p;
        p0 += (a[j] == 0) ? p : 0.f;
        p1 += (a[j] == 1) ? p : 0.f;
        p2 += (a[j] == 2) ? p : 0.f;
    }
    #pragma unroll
    for (int o = 16; o; o >>= 1) {
        sum += __shfl_xor_sync(0xffffffffu, sum, o);
        p0  += __shfl_xor_sync(0xffffffffu, p0, o);
        p1  += __shfl_xor_sync(0xffffffffu, p1, o);
        p2  += __shfl_xor_sync(0xffffffffu, p2, o);
    }
    float inv = 1.f / sum;

    float* Prow = g_P + ((size_t)bh * 512 + q) * 512;
    #pragma unroll
    for (int j = 0; j < 4; j++) {
        float4 pv;
        pv.x = tf32_rna(x[j*4+0] * inv);
        pv.y = tf32_rna(x[j*4+1] * inv);
        pv.z = tf32_rna(x[j*4+2] * inv);
        pv.w = tf32_rna(x[j*4+3] * inv);
        *(float4*)&Prow[lane * 16 + j * 4] = pv;
    }
    if (lane == 0) {
        float4 pwv = make_float4(p0 * inv, p1 * inv, p2 * inv, 0.f);
        *(float4*)&g_PW[((size_t)bh * 512 + q) * 4] = pwv;
    }
}

// ---------------- KC: O = P V + pw . lnv -------------------------------------
// grid (8 q-tiles of 64, 48 bh), 256 threads, cp.async double-buffered k=32.
#define P_STRIDE 36
#define V_STRIDE 72
#define PV_STAGE (64 * P_STRIDE + 32 * V_STRIDE)   // 2304 + 2304 = 4608 floats
#define PV_SMEM_BYTES (2 * PV_STAGE * 4)           // 36864

__global__ __launch_bounds__(256, 2) void pv_kernel(float* __restrict__ out) {
    extern __shared__ float sm[];

    int bh = blockIdx.y;
    int b = bh / HNUM, h = bh % HNUM;
    int q0 = blockIdx.x * 64;
    int t = threadIdx.x;
    int w = t >> 5;
    int lane = t & 31;
    int gid = lane >> 2;
    int tid4 = lane & 3;
    int wm = w >> 1;       // 0..3 (16 q rows)
    int wn = w & 1;        // 0..1 (32 d cols)

    const float* Pbase = g_P + ((size_t)bh * 512 + q0) * 512;
    const float* Vbase = g_V + (size_t)bh * 512 * 64;

    auto load_chunk = [&](int c, int s) {
        int k0 = c * 32;
        float* sP = sm + s * PV_STAGE;
        float* sV = sP + 64 * P_STRIDE;
        #pragma unroll
        for (int it = 0; it < 2; it++) {           // P: 64 rows x 8 float4
            int idx = it * 256 + t;
            int r = idx >> 3, c4 = (idx & 7) << 2;
            uint32_t dst = (uint32_t)__cvta_generic_to_shared(&sP[r * P_STRIDE + c4]);
            CP_ASYNC16(dst, &Pbase[(size_t)r * 512 + k0 + c4]);
        }
        #pragma unroll
        for (int it = 0; it < 2; it++) {           // V: 32 rows x 16 float4
            int idx = it * 256 + t;
            int r = idx >> 4, c4 = (idx & 15) << 2;
            uint32_t dst = (uint32_t)__cvta_generic_to_shared(&sV[r * V_STRIDE + c4]);
            CP_ASYNC16(dst, &Vbase[(size_t)(k0 + r) * 64 + c4]);
        }
        CP_COMMIT();
    };

    float acc[4][4];
    #pragma unroll
    for (int nt = 0; nt < 4; nt++)
        #pragma unroll
        for (int f = 0; f < 4; f++) acc[nt][f] = 0.f;

    load_chunk(0, 0);
    load_chunk(1, 1);
    CP_WAIT1();
    __syncthreads();

    for (int c = 0; c < 16; c++) {
        int s = c & 1;
        const float* sP = sm + s * PV_STAGE;
        const float* sV = sP + 64 * P_STRIDE;
        #pragma unroll
        for (int ks = 0; ks < 4; ks++) {
            int k = ks * 8 + tid4;
            float afr[4];
            int r = wm * 16 + gid;
            afr[0] = sP[r * P_STRIDE + k];
            afr[1] = sP[(r + 8) * P_STRIDE + k];
            afr[2] = sP[r * P_STRIDE + k + 4];
            afr[3] = sP[(r + 8) * P_STRIDE + k + 4];
            #pragma unroll
            for (int nt = 0; nt < 4; nt++) {
                int n = wn * 32 + nt * 8 + gid;
                float bfr[2];
                bfr[0] = tf32_rna(sV[k * V_STRIDE + n]);
                bfr[1] = tf32_rna(sV[(k + 4) * V_STRIDE + n]);
                MMA_TF32(acc[nt], afr, bfr);
            }
        }
        __syncthreads();
        if (c + 2 < 16) {
            load_chunk(c + 2, s);
            CP_WAIT1();
        } else {
            CP_WAIT0();
        }
        __syncthreads();
    }

    // epilogue: += pw . lnv, write out
    int r0 = wm * 16 + gid, r1 = r0 + 8;
    float4 pw0 = *(float4*)&g_PW[((size_t)bh * 512 + q0 + r0) * 4];
    float4 pw1 = *(float4*)&g_PW[((size_t)bh * 512 + q0 + r1) * 4];
    #pragma unroll
    for (int nt = 0; nt < 4; nt++) {
        int col = wn * 32 + nt * 8 + tid4 * 2;
        float l0a = g_lnv[col],       l0b = g_lnv[col + 1];
        float l1a = g_lnv[64 + col],  l1b = g_lnv[64 + col + 1];
        float l2a = g_lnv[128 + col], l2b = g_lnv[128 + col + 1];
        float2 v0, v1;
        v0.x = acc[nt][0] + pw0.x * l0a + pw0.y * l1a + pw0.z * l2a;
        v0.y = acc[nt][1] + pw0.x * l0b + pw0.y * l1b + pw0.z * l2b;
        v1.x = acc[nt][2] + pw1.x * l0a + pw1.y * l1a + pw1.z * l2a;
        v1.y = acc[nt][3] + pw1.x * l0b + pw1.y * l1b + pw1.z * l2b;
        *(float2*)&out[(size_t)(b * 512 + q0 + r0) * 768 + h * 64 + col] = v0;
        *(float2*)&out[(size_t)(b * 512 + q0 + r1) * 768 + h * 64 + col] = v1;
    }
}

// ---------------- launcher ----------------------------------------------------
extern "C" void kernel_launch(void* const* d_in, const int* in_sizes, int n_in,
                              void* d_out, int out_size) {
    const float* hidden = (const float*)d_in[0];
    const float* ctx    = (const float*)d_in[1];
    const float* mask   = (const float*)d_in[2];
    const int*   arc    = (const int*)d_in[3];
    const float* Wq = (const float*)d_in[4];  const float* bq = (const float*)d_in[5];
    const float* Wk = (const float*)d_in[6];  const float* bk = (const float*)d_in[7];
    const float* Wv = (const float*)d_in[8];  const float* bv = (const float*)d_in[9];
    const float* dpk = (const float*)d_in[10]; const float* dpv = (const float*)d_in[11];
    const float* lkg = (const float*)d_in[12]; const float* lkb = (const float*)d_in[13];
    const float* lvg = (const float*)d_in[14]; const float* lvb = (const float*)d_in[15];
    float* out = (float*)d_out;

    ln_prep_kernel<<<1, 192>>>(dpk, dpv, lkg, lkb, lvg, lvb);
    arc_pack_kernel<<<1024, 256>>>(arc);

    cudaFuncSetAttribute(qkv_gemm_mma_kernel, cudaFuncAttributeMaxDynamicSharedMemorySize,
                         GEMM_SMEM_BYTES);
    qkv_gemm_mma_kernel<<<dim3(16, 6, 3), 256, GEMM_SMEM_BYTES>>>(
        hidden, ctx, Wq, bq, Wk, bk, Wv, bv);

    cudaFuncSetAttribute(qk_kernel, cudaFuncAttributeMaxDynamicSharedMemorySize,
                         QK_SMEM_BYTES);
    qk_kernel<<<dim3(4, 4, 48), 256, QK_SMEM_BYTES>>>();

    softmax_kernel<<<dim3(64, 48), 256>>>(mask);

    cudaFuncSetAttribute(pv_kernel, cudaFuncAttributeMaxDynamicSharedMemorySize,
                         PV_SMEM_BYTES);
    pv_kernel<<<dim3(8, 48), 256, PV_SMEM_BYTES>>>(out);
}